// round 8
// baseline (speedup 1.0000x reference)
#include <cuda_runtime.h>
#include <cuda_fp16.h>
#include <cstdint>
#include <cstddef>

// Problem constants
#define TT   1024
#define BB   512
#define II   32
#define HH   256
#define OO   32
#define KDIM 288
#define NCHUNK 18        // 288/16 k-chunks per pass

#define NGRP 16          // batch groups (32 rows each)
#define BT   32
#define NTHR 256         // 8 warps, warp w owns D rows [16w,16w+16)
#define MROWS 128        // gate rows per CTA, r = 4*j + gate
#define KP   296         // padded halfs per row (592 B: rows mod 128 all distinct)
#define RB   592         // row bytes

typedef unsigned long long ull;

// Persistent scratch (no allocation allowed)
__device__ __align__(16) float g_h[2][NGRP][BT][HH];   // hidden state [par][grp][b][j]
__device__ unsigned            g_bar[NGRP];

__global__ void init_kernel() {
    int idx = blockIdx.x * blockDim.x + threadIdx.x;
    if (idx < NGRP * BT * HH) ((float*)g_h)[idx] = 0.0f;   // zero h(0) (parity 0)
    if (idx < NGRP) g_bar[idx] = 0u;
}

// ---------- helpers ----------
__device__ __forceinline__ void ffma2(ull& acc, ull a, ull b) {
    asm("fma.rn.f32x2 %0, %1, %2, %0;" : "+l"(acc) : "l"(a), "l"(b));
}
__device__ __forceinline__ void add2(ull& a, ull b) {
    asm("add.rn.f32x2 %0, %0, %1;" : "+l"(a) : "l"(b));
}
__device__ __forceinline__ ull pack2(float a, float b) {
    ull r; asm("mov.b64 %0, {%1, %2};" : "=l"(r) : "f"(a), "f"(b)); return r;
}
__device__ __forceinline__ float2 unpack2(ull v) {
    float2 r; asm("mov.b64 {%0, %1}, %2;" : "=f"(r.x), "=f"(r.y) : "l"(v)); return r;
}
__device__ __forceinline__ unsigned ld_acquire_u32(const unsigned* p) {
    unsigned v;
    asm volatile("ld.acquire.gpu.u32 %0, [%1];" : "=r"(v) : "l"(p));
    return v;
}
__device__ __forceinline__ void red_release_add(unsigned* p, unsigned v) {
    asm volatile("red.release.gpu.global.add.u32 [%0], %1;" :: "l"(p), "r"(v) : "memory");
}
__device__ __forceinline__ float sigf(float x) {
    return __fdividef(1.0f, 1.0f + __expf(-x));
}
__device__ __forceinline__ float tanh_acc(float x) {
    float ax = fabsf(x);
    float e  = __expf(-2.0f * ax);
    float r  = __fdividef(1.0f - e, 1.0f + e);
    return copysignf(r, x);
}
__device__ __forceinline__ uint32_t h2u(__half2 h) { return *reinterpret_cast<uint32_t*>(&h); }

__device__ __forceinline__ void ldsm4(uint32_t& r0, uint32_t& r1, uint32_t& r2, uint32_t& r3,
                                      uint32_t addr) {
    asm volatile("ldmatrix.sync.aligned.m8n8.x4.shared.b16 {%0,%1,%2,%3}, [%4];"
                 : "=r"(r0), "=r"(r1), "=r"(r2), "=r"(r3) : "r"(addr));
}
__device__ __forceinline__ void mma16816(float* d, uint32_t a0, uint32_t a1, uint32_t a2,
                                         uint32_t a3, uint32_t b0, uint32_t b1) {
    asm volatile("mma.sync.aligned.m16n8k16.row.col.f32.f16.f16.f32 "
                 "{%0,%1,%2,%3}, {%4,%5,%6,%7}, {%8,%9}, {%0,%1,%2,%3};"
                 : "+f"(d[0]), "+f"(d[1]), "+f"(d[2]), "+f"(d[3])
                 : "r"(a0), "r"(a1), "r"(a2), "r"(a3), "r"(b0), "r"(b1));
}

// smem byte offsets
#define OFF_A_HI   0          // half[128][296] = 75776
#define OFF_A_LO   75776
#define OFF_B_HI   151552     // half[32][296] = 18944
#define OFF_B_LO   170496
#define OFF_GATES  189440     // float[128][33] = 16896
#define OFF_HT     206336     // float[32][33]  = 4224
#define OFF_WOUT   210560     // ull[128 jp][4 o] = 4096
#define OFF_BOUT   214656     // float[4]
#define SMEM_BYTES 214688

__global__ void __launch_bounds__(NTHR, 1)
lstm_kernel(const float* __restrict__ x, const float* __restrict__ phys,
            const float* __restrict__ Wih, const float* __restrict__ Whh,
            const float* __restrict__ bih, const float* __restrict__ bhh,
            const float* __restrict__ Wout, const float* __restrict__ bout,
            float* __restrict__ out) {
    extern __shared__ __align__(128) char smem[];
    uint32_t sbase;
    asm("{ .reg .u64 t; cvta.to.shared.u64 t, %1; cvt.u32.u64 %0, t; }" : "=r"(sbase) : "l"(smem));

    float* gates  = (float*)(smem + OFF_GATES);
    float* htile  = (float*)(smem + OFF_HT);
    ull*   woutP  = (ull*)(smem + OFF_WOUT);
    float* bout_s = (float*)(smem + OFF_BOUT);

    const int tid  = threadIdx.x;
    const int cta  = blockIdx.x;
    const int grp  = cta >> 3;
    const int g8   = cta & 7;
    const int b0   = grp * BT;
    const int j0   = g8 * 32;
    const int w    = tid >> 5;
    const int lane = tid & 31;
    const int b    = tid >> 3;     // batch row 0..31 (staging/epilogue map)
    const int s    = tid & 7;      // k-slice 0..7

    // ---- zero B tiles once (pad cols 288..295 stay 0 forever) ----
    for (int i = tid; i < (2 * 18944) / 16; i += NTHR)
        ((uint4*)(smem + OFF_B_HI))[i] = make_uint4(0, 0, 0, 0);

    // ---- A = weights fp16 hi/lo, row r = 4j+gate, 592B stride ----
    for (int i = tid; i < MROWS * KP; i += NTHR) {
        int r = i / KP, k = i - r * KP;
        int j = r >> 2, g = r & 3;
        int grow = g * HH + j0 + j;
        float v = 0.0f;
        if (k < HH)        v = Whh[grow * HH + k];
        else if (k < KDIM) v = Wih[grow * II + (k - HH)];
        __half h = __float2half_rn(v);
        __half l = __float2half_rn(v - __half2float(h));
        *(__half*)(smem + OFF_A_HI + r * RB + k * 2) = h;
        *(__half*)(smem + OFF_A_LO + r * RB + k * 2) = l;
    }
    // Wout pairs: woutP[jp*4+o] = (Wout[o][2jp], Wout[o][2jp+1])
    for (int i = tid; i < 128 * 4; i += NTHR) {
        int jp = i >> 2, o = i & 3;
        woutP[i] = pack2(Wout[(g8 * 4 + o) * HH + 2 * jp],
                         Wout[(g8 * 4 + o) * HH + 2 * jp + 1]);
    }
    if (tid < 4) bout_s[tid] = bout[g8 * 4 + tid];

    // MMA fragment lane mapping
    const int m  = lane >> 3;        // matrix index for ldmatrix x4
    const int r8 = lane & 7;
    const int gq = lane >> 2;        // D row group
    const int tg = lane & 3;         // D col pair
    const uint32_t aHi = sbase + OFF_A_HI + (16 * w + ((m & 1) << 3) + r8) * RB + ((m >> 1) << 4);
    const uint32_t aLo = aHi + (OFF_A_LO - OFF_A_HI);
    const uint32_t bHi = sbase + OFF_B_HI + (((m >> 1) << 3) + r8) * RB + ((m & 1) << 4);
    const uint32_t bLo = bHi + (OFF_B_LO - OFF_B_HI);

    // bias folded into D-register init (rows 16w+gq, 16w+gq+8)
    float bias_lo, bias_hi;
    {
        int r1 = 16 * w + gq, r2 = r1 + 8;
        int j1 = r1 >> 2, gg1 = r1 & 3, j2 = r2 >> 2, gg2 = r2 & 3;
        bias_lo = bih[gg1 * HH + j0 + j1] + bhh[gg1 * HH + j0 + j1];
        bias_hi = bih[gg2 * HH + j0 + j2] + bhh[gg2 * HH + j0 + j2];
    }

    float c[4] = {0.f, 0.f, 0.f, 0.f};    // cell state: (j=tid>>3, batches 4s..4s+4)
    __syncthreads();

    for (int t = 0; t <= TT; ++t) {
        // ---- group barrier: per-warp acquire spin ----
        if (t > 0) {
            if (lane == 0) {
                unsigned target = 8u * (unsigned)t;
                while (ld_acquire_u32(&g_bar[grp]) < target) { }
            }
            __syncwarp();
        }

        // ---- stage h(t): LDG fp32 -> fp16 hi/lo STS + out-proj partials ----
        ull pacc[4] = {0ull, 0ull, 0ull, 0ull};
        {
            const float* hrow = &g_h[t & 1][grp][b][0] + s * 32;
            char* dhi = smem + OFF_B_HI + b * RB + s * 64;
            char* dlo = smem + OFF_B_LO + b * RB + s * 64;
#pragma unroll
            for (int mm = 0; mm < 4; ++mm) {
                float4 v0 = *(const float4*)(hrow + mm * 8);
                float4 v1 = *(const float4*)(hrow + mm * 8 + 4);
                int jp = s * 16 + mm * 4;
                ull vp0 = pack2(v0.x, v0.y), vp1 = pack2(v0.z, v0.w);
                ull vp2 = pack2(v1.x, v1.y), vp3 = pack2(v1.z, v1.w);
#pragma unroll
                for (int o = 0; o < 4; ++o) {
                    ffma2(pacc[o], vp0, woutP[(jp + 0) * 4 + o]);
                    ffma2(pacc[o], vp1, woutP[(jp + 1) * 4 + o]);
                    ffma2(pacc[o], vp2, woutP[(jp + 2) * 4 + o]);
                    ffma2(pacc[o], vp3, woutP[(jp + 3) * 4 + o]);
                }
                __half2 a0 = __floats2half2_rn(v0.x, v0.y);
                __half2 a1 = __floats2half2_rn(v0.z, v0.w);
                __half2 a2 = __floats2half2_rn(v1.x, v1.y);
                __half2 a3 = __floats2half2_rn(v1.z, v1.w);
                float2 f0 = __half22float2(a0), f1 = __half22float2(a1);
                float2 f2 = __half22float2(a2), f3 = __half22float2(a3);
                __half2 l0 = __floats2half2_rn(v0.x - f0.x, v0.y - f0.y);
                __half2 l1 = __floats2half2_rn(v0.z - f1.x, v0.w - f1.y);
                __half2 l2 = __floats2half2_rn(v1.x - f2.x, v1.y - f2.y);
                __half2 l3 = __floats2half2_rn(v1.z - f3.x, v1.w - f3.y);
                *(uint4*)(dhi + mm * 16) = make_uint4(h2u(a0), h2u(a1), h2u(a2), h2u(a3));
                *(uint4*)(dlo + mm * 16) = make_uint4(h2u(l0), h2u(l1), h2u(l2), h2u(l3));
            }
        }
        if (t < TT) {   // stage x(t) into B cols 256..287
            float4 xv = *(const float4*)(x + ((size_t)t * BB + b0 + b) * II + s * 4);
            __half2 xh0 = __floats2half2_rn(xv.x, xv.y);
            __half2 xh1 = __floats2half2_rn(xv.z, xv.w);
            float2 xf0 = __half22float2(xh0), xf1 = __half22float2(xh1);
            __half2 xl0 = __floats2half2_rn(xv.x - xf0.x, xv.y - xf0.y);
            __half2 xl1 = __floats2half2_rn(xv.z - xf1.x, xv.w - xf1.y);
            uint32_t off = b * RB + 512 + s * 8;
            *(uint2*)(smem + OFF_B_HI + off) = make_uint2(h2u(xh0), h2u(xh1));
            *(uint2*)(smem + OFF_B_LO + off) = make_uint2(h2u(xl0), h2u(xl1));
        }

        // ---- out-projection finalize for step t-1 (warp-local, pre-sync) ----
        if (t > 0) {
#pragma unroll
            for (int d = 1; d < 8; d <<= 1)
#pragma unroll
                for (int o = 0; o < 4; ++o) {
                    ull other = __shfl_xor_sync(0xffffffffu, pacc[o], d);
                    add2(pacc[o], other);
                }
            if (s < 4) {
                float2 pf = unpack2(pacc[s]);
                float rnn = pf.x + pf.y + bout_s[s];
                int tm1 = t - 1, bg = b0 + b, oc = g8 * 4 + s;
                float ph = phys[((size_t)tm1 * BB + bg) * OO + oc];
                size_t oi = ((size_t)bg * TT + tm1) * OO + oc;
                out[oi] = ph + rnn;                              // full_pred [B,T,O]
                out[(size_t)BB * TT * OO + oi] = rnn;            // rnn_pred  [B,T,O]
            }
        }
        if (t == TT) break;
        __syncthreads();

        // ---- gate GEMM: 3-pass fp16-split mma.sync ----
        float d[4][4];
#pragma unroll
        for (int nt = 0; nt < 4; ++nt) {
            d[nt][0] = bias_lo; d[nt][1] = bias_lo;
            d[nt][2] = bias_hi; d[nt][3] = bias_hi;
        }
#pragma unroll
        for (int pass = 0; pass < 3; ++pass) {
            uint32_t aB = (pass < 2) ? aHi : aLo;
            uint32_t bB = (pass == 1) ? bLo : bHi;
#pragma unroll
            for (int kc = 0; kc < NCHUNK; ++kc) {
                uint32_t a0, a1, a2, a3, q0, q1, q2, q3;
                ldsm4(a0, a1, a2, a3, aB + kc * 32);
                ldsm4(q0, q1, q2, q3, bB + kc * 32);             // b-tiles 0,1
                mma16816(d[0], a0, a1, a2, a3, q0, q1);
                mma16816(d[1], a0, a1, a2, a3, q2, q3);
                ldsm4(q0, q1, q2, q3, bB + 16 * RB + kc * 32);   // b-tiles 2,3
                mma16816(d[2], a0, a1, a2, a3, q0, q1);
                mma16816(d[3], a0, a1, a2, a3, q2, q3);
            }
        }
        // D -> gates[row][batch] (stride 33)
        {
            float* glo = gates + (16 * w + gq) * 33 + 2 * tg;
            float* ghi = glo + 8 * 33;
#pragma unroll
            for (int nt = 0; nt < 4; ++nt) {
                glo[8 * nt] = d[nt][0]; glo[8 * nt + 1] = d[nt][1];
                ghi[8 * nt] = d[nt][2]; ghi[8 * nt + 1] = d[nt][3];
            }
        }
        __syncthreads();

        // ---- LSTM epilogue: thread = (j = tid>>3, batches 4s..4s+4) ----
        {
            int j = tid >> 3;
            const float* gr = gates + (4 * j) * 33;
#pragma unroll
            for (int i = 0; i < 4; ++i) {
                int bb = s * 4 + i;
                float gi = gr[bb];
                float gf = gr[33 + bb];
                float gg = gr[66 + bb];
                float go = gr[99 + bb];
                float ig = sigf(gi), fg = sigf(gf);
                float gt = tanh_acc(gg), og = sigf(go);
                float cn = fg * c[i] + ig * gt;
                c[i] = cn;
                htile[bb * 33 + j] = og * tanh_acc(cn);
            }
        }
        __syncthreads();

        // ---- h writeback: htile -> g_h[(t+1)&1][grp][b][j0..] ----
        {
            float f0 = htile[b * 33 + 4 * s + 0];
            float f1 = htile[b * 33 + 4 * s + 1];
            float f2 = htile[b * 33 + 4 * s + 2];
            float f3 = htile[b * 33 + 4 * s + 3];
            *(float4*)(&g_h[(t + 1) & 1][grp][b][j0 + 4 * s]) = make_float4(f0, f1, f2, f3);
        }
        __syncthreads();
        if (tid == 0) red_release_add(&g_bar[grp], 1u);
    }
}

extern "C" void kernel_launch(void* const* d_in, const int* in_sizes, int n_in,
                              void* d_out, int out_size) {
    const float* x    = (const float*)d_in[0];
    const float* phys = (const float*)d_in[1];
    const float* Wih  = (const float*)d_in[2];
    const float* Whh  = (const float*)d_in[3];
    const float* bih  = (const float*)d_in[4];
    const float* bhh  = (const float*)d_in[5];
    const float* Wout = (const float*)d_in[6];
    const float* bout = (const float*)d_in[7];
    float* out = (float*)d_out;

    cudaFuncSetAttribute(lstm_kernel,
                         cudaFuncAttributeMaxDynamicSharedMemorySize,
                         SMEM_BYTES);

    init_kernel<<<(NGRP * BT * HH + 255) / 256, 256>>>();
    lstm_kernel<<<NGRP * 8, NTHR, SMEM_BYTES>>>(x, phys, Wih, Whh, bih, bhh,
                                                Wout, bout, out);
}

// round 9
// speedup vs baseline: 1.5806x; 1.5806x over previous
#include <cuda_runtime.h>
#include <cuda_fp16.h>
#include <cstdint>
#include <cstddef>

// Problem constants
#define TT   1024
#define BB   512
#define II   32
#define HH   256
#define OO   32
#define KDIM 288
#define NCHUNK 18        // 288/16 k-chunks

#define NGRP 16          // batch groups (32 rows each)
#define BT   32
#define NTHR 256         // 8 warps, warp w owns D rows [16w,16w+16)
#define MROWS 128        // gate rows per CTA, r = 4*j + gate
#define KP   296         // padded halfs per row
#define RB   592         // row bytes (rows mod 128 all distinct -> conflict-free ldsm)

typedef unsigned long long ull;

// Persistent scratch (no allocation allowed)
__device__ __align__(16) float g_h[2][NGRP][BT][HH];       // hidden state [par][grp][b][j]
__device__ __align__(16) float g_part[2][NGRP][8][BT][OO]; // out-proj partials [par][grp][cta][b][o]
__device__ unsigned            g_bar[NGRP];

__global__ void init_kernel() {
    int idx = blockIdx.x * blockDim.x + threadIdx.x;
    if (idx < NGRP * BT * HH) ((float*)g_h)[idx] = 0.0f;   // zero h(0) (parity 0)
    if (idx < NGRP) g_bar[idx] = 0u;
}

// ---------- helpers ----------
__device__ __forceinline__ void ffma2(ull& acc, ull a, ull b) {
    asm("fma.rn.f32x2 %0, %1, %2, %0;" : "+l"(acc) : "l"(a), "l"(b));
}
__device__ __forceinline__ ull pack2(float a, float b) {
    ull r; asm("mov.b64 %0, {%1, %2};" : "=l"(r) : "f"(a), "f"(b)); return r;
}
__device__ __forceinline__ float2 unpack2(ull v) {
    float2 r; asm("mov.b64 {%0, %1}, %2;" : "=f"(r.x), "=f"(r.y) : "l"(v)); return r;
}
__device__ __forceinline__ unsigned ld_acquire_u32(const unsigned* p) {
    unsigned v;
    asm volatile("ld.acquire.gpu.u32 %0, [%1];" : "=r"(v) : "l"(p));
    return v;
}
__device__ __forceinline__ void red_release_add(unsigned* p, unsigned v) {
    asm volatile("red.release.gpu.global.add.u32 [%0], %1;" :: "l"(p), "r"(v) : "memory");
}
__device__ __forceinline__ float sigf(float x) {
    return __fdividef(1.0f, 1.0f + __expf(-x));
}
__device__ __forceinline__ float tanh_acc(float x) {
    float ax = fabsf(x);
    float e  = __expf(-2.0f * ax);
    float r  = __fdividef(1.0f - e, 1.0f + e);
    return copysignf(r, x);
}
__device__ __forceinline__ uint32_t h2u(__half2 h) { return *reinterpret_cast<uint32_t*>(&h); }

__device__ __forceinline__ void ldsm4(uint32_t* r, uint32_t addr) {
    asm volatile("ldmatrix.sync.aligned.m8n8.x4.shared.b16 {%0,%1,%2,%3}, [%4];"
                 : "=r"(r[0]), "=r"(r[1]), "=r"(r[2]), "=r"(r[3]) : "r"(addr));
}
__device__ __forceinline__ void mma16816(float* d, const uint32_t* a, uint32_t b0, uint32_t b1) {
    asm volatile("mma.sync.aligned.m16n8k16.row.col.f32.f16.f16.f32 "
                 "{%0,%1,%2,%3}, {%4,%5,%6,%7}, {%8,%9}, {%0,%1,%2,%3};"
                 : "+f"(d[0]), "+f"(d[1]), "+f"(d[2]), "+f"(d[3])
                 : "r"(a[0]), "r"(a[1]), "r"(a[2]), "r"(a[3]), "r"(b0), "r"(b1));
}

// smem byte offsets
#define OFF_A_HI   0          // half[128][296] = 75776
#define OFF_A_LO   75776
#define OFF_B_HI   151552     // half[32][296] = 18944
#define OFF_B_LO   170496
#define OFF_GATES  189440     // float[128][36] = 18432
#define OFF_HT     207872     // float[32][34]  = 4352
#define OFF_WOUT2  212224     // ull[32 o][17]  = 4352
#define OFF_BOUT   216576     // float[4]
#define SMEM_BYTES 216608

__global__ void __launch_bounds__(NTHR, 1)
lstm_kernel(const float* __restrict__ x, const float* __restrict__ phys,
            const float* __restrict__ Wih, const float* __restrict__ Whh,
            const float* __restrict__ bih, const float* __restrict__ bhh,
            const float* __restrict__ Wout, const float* __restrict__ bout,
            float* __restrict__ out) {
    extern __shared__ __align__(128) char smem[];
    uint32_t sbase;
    asm("{ .reg .u64 t; cvta.to.shared.u64 t, %1; cvt.u32.u64 %0, t; }" : "=r"(sbase) : "l"(smem));

    float* gates   = (float*)(smem + OFF_GATES);
    float* htile   = (float*)(smem + OFF_HT);
    ull*   wout2_s = (ull*)(smem + OFF_WOUT2);
    float* bout_s  = (float*)(smem + OFF_BOUT);

    const int tid  = threadIdx.x;
    const int cta  = blockIdx.x;
    const int grp  = cta >> 3;
    const int g8   = cta & 7;
    const int b0   = grp * BT;
    const int j0   = g8 * 32;
    const int w    = tid >> 5;
    const int lane = tid & 31;
    const int b    = tid >> 3;     // batch row 0..31 (staging/epilogue map)
    const int s    = tid & 7;      // k-slice 0..7

    // ---- zero B tiles once (pad cols 288..295 stay 0 forever) ----
    for (int i = tid; i < (2 * 18944) / 16; i += NTHR)
        ((uint4*)(smem + OFF_B_HI))[i] = make_uint4(0, 0, 0, 0);

    // ---- A = weights fp16 hi/lo, row r = 4j+gate, 592B stride ----
    for (int i = tid; i < MROWS * KP; i += NTHR) {
        int r = i / KP, k = i - r * KP;
        int j = r >> 2, g = r & 3;
        int grow = g * HH + j0 + j;
        float v = 0.0f;
        if (k < HH)        v = Whh[grow * HH + k];
        else if (k < KDIM) v = Wih[grow * II + (k - HH)];
        __half h = __float2half_rn(v);
        __half l = __float2half_rn(v - __half2float(h));
        *(__half*)(smem + OFF_A_HI + r * RB + k * 2) = h;
        *(__half*)(smem + OFF_A_LO + r * RB + k * 2) = l;
    }
    // Wout pairs over OWN j-slice, all 32 o: wout2_s[o][jp] = (Wout[o][j0+2jp], Wout[o][j0+2jp+1])
    for (int i = tid; i < 32 * 16; i += NTHR) {
        int o = i >> 4, jp = i & 15;
        wout2_s[o * 17 + jp] = pack2(Wout[o * HH + j0 + 2 * jp],
                                     Wout[o * HH + j0 + 2 * jp + 1]);
    }
    if (tid < 4) bout_s[tid] = bout[g8 * 4 + tid];

    // MMA fragment lane mapping (identical to R8, which validated)
    const int m  = lane >> 3;
    const int r8 = lane & 7;
    const int gq = lane >> 2;
    const int tg = lane & 3;
    const uint32_t aHi = sbase + OFF_A_HI + (16 * w + ((m & 1) << 3) + r8) * RB + ((m >> 1) << 4);
    const uint32_t aLo = aHi + (OFF_A_LO - OFF_A_HI);
    const uint32_t bHi = sbase + OFF_B_HI + (((m >> 1) << 3) + r8) * RB + ((m & 1) << 4);
    const uint32_t bLo = bHi + (OFF_B_LO - OFF_B_HI);

    // bias folded into D-register init (rows 16w+gq, 16w+gq+8)
    float bias_lo, bias_hi;
    {
        int r1 = 16 * w + gq, r2 = r1 + 8;
        int j1 = r1 >> 2, gg1 = r1 & 3, j2 = r2 >> 2, gg2 = r2 & 3;
        bias_lo = bih[gg1 * HH + j0 + j1] + bhh[gg1 * HH + j0 + j1];
        bias_hi = bih[gg2 * HH + j0 + j2] + bhh[gg2 * HH + j0 + j2];
    }

    float c[4] = {0.f, 0.f, 0.f, 0.f};    // cell state: (j=tid>>3, batches 4s..4s+4)
    __syncthreads();

    for (int t = 0; t <= TT; ++t) {
        // ---- peer-independent prefetches BEFORE the spin ----
        float4 xv = make_float4(0.f, 0.f, 0.f, 0.f);
        if (t < TT)
            xv = *(const float4*)(x + ((size_t)t * BB + b0 + b) * II + s * 4);
        float phv = 0.0f;
        if (t > 0 && tid < 128)
            phv = phys[((size_t)(t - 1) * BB + b0 + (tid >> 2)) * OO + g8 * 4 + (tid & 3)];

        // ---- group barrier: per-warp acquire spin ----
        if (t > 0) {
            if (lane == 0) {
                unsigned target = 8u * (unsigned)t;
                while (ld_acquire_u32(&g_bar[grp]) < target) { }
            }
            __syncwarp();
        }

        if (t < TT) {
            // ---- stage h(t): LDG fp32 -> fp16 hi/lo STS ----
            const float* hrow = &g_h[t & 1][grp][b][0] + s * 32;
            char* dhi = smem + OFF_B_HI + b * RB + s * 64;
            char* dlo = smem + OFF_B_LO + b * RB + s * 64;
#pragma unroll
            for (int mm = 0; mm < 4; ++mm) {
                float4 v0 = *(const float4*)(hrow + mm * 8);
                float4 v1 = *(const float4*)(hrow + mm * 8 + 4);
                __half2 a0 = __floats2half2_rn(v0.x, v0.y);
                __half2 a1 = __floats2half2_rn(v0.z, v0.w);
                __half2 a2 = __floats2half2_rn(v1.x, v1.y);
                __half2 a3 = __floats2half2_rn(v1.z, v1.w);
                float2 f0 = __half22float2(a0), f1 = __half22float2(a1);
                float2 f2 = __half22float2(a2), f3 = __half22float2(a3);
                __half2 l0 = __floats2half2_rn(v0.x - f0.x, v0.y - f0.y);
                __half2 l1 = __floats2half2_rn(v0.z - f1.x, v0.w - f1.y);
                __half2 l2 = __floats2half2_rn(v1.x - f2.x, v1.y - f2.y);
                __half2 l3 = __floats2half2_rn(v1.z - f3.x, v1.w - f3.y);
                *(uint4*)(dhi + mm * 16) = make_uint4(h2u(a0), h2u(a1), h2u(a2), h2u(a3));
                *(uint4*)(dlo + mm * 16) = make_uint4(h2u(l0), h2u(l1), h2u(l2), h2u(l3));
            }
            // stage x(t) into B cols 256..287
            __half2 xh0 = __floats2half2_rn(xv.x, xv.y);
            __half2 xh1 = __floats2half2_rn(xv.z, xv.w);
            float2 xf0 = __half22float2(xh0), xf1 = __half22float2(xh1);
            __half2 xl0 = __floats2half2_rn(xv.x - xf0.x, xv.y - xf0.y);
            __half2 xl1 = __floats2half2_rn(xv.z - xf1.x, xv.w - xf1.y);
            uint32_t off = b * RB + 512 + s * 8;
            *(uint2*)(smem + OFF_B_HI + off) = make_uint2(h2u(xh0), h2u(xh1));
            *(uint2*)(smem + OFF_B_LO + off) = make_uint2(h2u(xl0), h2u(xl1));
        }

        // ---- output for step t-1: sum 8 CTA partials (written before peers' release) ----
        if (t > 0 && tid < 128) {
            int bq = tid >> 2, o = tid & 3, oc = g8 * 4 + o;
            float rnn = bout_s[o];
            const float* pp = &g_part[t & 1][grp][0][bq][oc];
#pragma unroll
            for (int p = 0; p < 8; ++p) rnn += pp[(size_t)p * BT * OO];
            int tm1 = t - 1, bg = b0 + bq;
            size_t oi = ((size_t)bg * TT + tm1) * OO + oc;
            out[oi] = phv + rnn;                              // full_pred [B,T,O]
            out[(size_t)BB * TT * OO + oi] = rnn;             // rnn_pred  [B,T,O]
        }
        if (t == TT) break;
        __syncthreads();

        // ---- gate GEMM: 3-pass fp16-split, fragments loaded once per chunk ----
        float d[4][4];
#pragma unroll
        for (int nt = 0; nt < 4; ++nt) {
            d[nt][0] = bias_lo; d[nt][1] = bias_lo;
            d[nt][2] = bias_hi; d[nt][3] = bias_hi;
        }
#pragma unroll 3
        for (int kc = 0; kc < NCHUNK; ++kc) {
            uint32_t a[4], a2[4], qh[8], ql[8];
            ldsm4(a,      aHi + kc * 32);
            ldsm4(qh,     bHi + kc * 32);
            ldsm4(qh + 4, bHi + 16 * RB + kc * 32);
            ldsm4(ql,     bLo + kc * 32);
            ldsm4(ql + 4, bLo + 16 * RB + kc * 32);
            ldsm4(a2,     aLo + kc * 32);
            mma16816(d[0], a,  qh[0], qh[1]);
            mma16816(d[1], a,  qh[2], qh[3]);
            mma16816(d[2], a,  qh[4], qh[5]);
            mma16816(d[3], a,  qh[6], qh[7]);
            mma16816(d[0], a,  ql[0], ql[1]);
            mma16816(d[1], a,  ql[2], ql[3]);
            mma16816(d[2], a,  ql[4], ql[5]);
            mma16816(d[3], a,  ql[6], ql[7]);
            mma16816(d[0], a2, qh[0], qh[1]);
            mma16816(d[1], a2, qh[2], qh[3]);
            mma16816(d[2], a2, qh[4], qh[5]);
            mma16816(d[3], a2, qh[6], qh[7]);
        }
        // D -> gates[row][batch] (stride 36)
        {
            float* glo = gates + (16 * w + gq) * 36 + 2 * tg;
            float* ghi = glo + 8 * 36;
#pragma unroll
            for (int nt = 0; nt < 4; ++nt) {
                glo[8 * nt] = d[nt][0]; glo[8 * nt + 1] = d[nt][1];
                ghi[8 * nt] = d[nt][2]; ghi[8 * nt + 1] = d[nt][3];
            }
        }
        __syncthreads();

        // ---- LSTM epilogue: thread = (j = tid>>3, batches 4s..4s+4) ----
        {
            int j = tid >> 3;
            const float* gr = gates + (4 * j) * 36 + 4 * s;
            float4 vi = *(const float4*)(gr);
            float4 vf = *(const float4*)(gr + 36);
            float4 vg = *(const float4*)(gr + 72);
            float4 vo = *(const float4*)(gr + 108);
            float gi_[4] = {vi.x, vi.y, vi.z, vi.w};
            float gf_[4] = {vf.x, vf.y, vf.z, vf.w};
            float gg_[4] = {vg.x, vg.y, vg.z, vg.w};
            float go_[4] = {vo.x, vo.y, vo.z, vo.w};
#pragma unroll
            for (int i = 0; i < 4; ++i) {
                float ig = sigf(gi_[i]), fg = sigf(gf_[i]);
                float gt = tanh_acc(gg_[i]), og = sigf(go_[i]);
                float cn = fg * c[i] + ig * gt;
                c[i] = cn;
                htile[(4 * s + i) * 34 + j] = og * tanh_acc(cn);
            }
        }
        __syncthreads();

        // ---- h writeback (coalesced) + out-proj partial from htile ----
        {
            float f0 = htile[b * 34 + 4 * s + 0];
            float f1 = htile[b * 34 + 4 * s + 1];
            float f2 = htile[b * 34 + 4 * s + 2];
            float f3 = htile[b * 34 + 4 * s + 3];
            *(float4*)(&g_h[(t + 1) & 1][grp][b][j0 + 4 * s]) = make_float4(f0, f1, f2, f3);
        }
        {
            int o4 = s * 4;
            const ull* hrow2 = (const ull*)(htile + b * 34);
            ull pa0 = 0ull, pa1 = 0ull, pa2 = 0ull, pa3 = 0ull;
#pragma unroll
            for (int jp = 0; jp < 16; ++jp) {
                ull h2 = hrow2[jp];
                ffma2(pa0, h2, wout2_s[(o4 + 0) * 17 + jp]);
                ffma2(pa1, h2, wout2_s[(o4 + 1) * 17 + jp]);
                ffma2(pa2, h2, wout2_s[(o4 + 2) * 17 + jp]);
                ffma2(pa3, h2, wout2_s[(o4 + 3) * 17 + jp]);
            }
            float2 q0 = unpack2(pa0), q1 = unpack2(pa1);
            float2 q2 = unpack2(pa2), q3 = unpack2(pa3);
            *(float4*)(&g_part[(t + 1) & 1][grp][g8][b][o4]) =
                make_float4(q0.x + q0.y, q1.x + q1.y, q2.x + q2.y, q3.x + q3.y);
        }
        __syncthreads();
        if (tid == 0) red_release_add(&g_bar[grp], 1u);
    }
}

extern "C" void kernel_launch(void* const* d_in, const int* in_sizes, int n_in,
                              void* d_out, int out_size) {
    const float* x    = (const float*)d_in[0];
    const float* phys = (const float*)d_in[1];
    const float* Wih  = (const float*)d_in[2];
    const float* Whh  = (const float*)d_in[3];
    const float* bih  = (const float*)d_in[4];
    const float* bhh  = (const float*)d_in[5];
    const float* Wout = (const float*)d_in[6];
    const float* bout = (const float*)d_in[7];
    float* out = (float*)d_out;

    cudaFuncSetAttribute(lstm_kernel,
                         cudaFuncAttributeMaxDynamicSharedMemorySize,
                         SMEM_BYTES);

    init_kernel<<<(NGRP * BT * HH + 255) / 256, 256>>>();
    lstm_kernel<<<NGRP * 8, NTHR, SMEM_BYTES>>>(x, phys, Wih, Whh, bih, bhh,
                                                Wout, bout, out);
}

// round 10
// speedup vs baseline: 1.6584x; 1.0492x over previous
#include <cuda_runtime.h>
#include <cuda_fp16.h>
#include <cstdint>
#include <cstddef>

// Problem constants
#define TT   1024
#define BB   512
#define II   32
#define HH   256
#define OO   32
#define KDIM 288
#define NCHUNK 18        // 288/16 k-chunks

#define NGRP 16          // batch groups (32 rows each)
#define BT   32
#define NTHR 256         // 8 warps, warp w owns D rows [16w,16w+16)
#define MROWS 128        // gate rows per CTA, r = 4*j + gate
#define KP   296         // padded halfs per row
#define RB   592         // row bytes (rows mod 128 all distinct -> conflict-free ldsm)

typedef unsigned long long ull;

// Persistent scratch (no allocation allowed)
__device__ __align__(16) __half g_hf16_hi[2][NGRP][BT][HH]; // h fp16 hi [par][grp][b][j]
__device__ __align__(16) __half g_hf16_lo[2][NGRP][BT][HH]; // h fp16 lo
__device__ __align__(16) float  g_part[2][NGRP][8][BT][OO]; // out-proj partials
__device__ unsigned             g_bar[NGRP];

__global__ void init_kernel() {
    int idx = blockIdx.x * blockDim.x + threadIdx.x;
    if (idx < 2 * NGRP * BT * HH / 2) {          // uint32 elements per array
        ((unsigned*)g_hf16_hi)[idx] = 0u;
        ((unsigned*)g_hf16_lo)[idx] = 0u;
    }
    if (idx < NGRP) g_bar[idx] = 0u;
}

// ---------- helpers ----------
__device__ __forceinline__ void ffma2(ull& acc, ull a, ull b) {
    asm("fma.rn.f32x2 %0, %1, %2, %0;" : "+l"(acc) : "l"(a), "l"(b));
}
__device__ __forceinline__ ull pack2(float a, float b) {
    ull r; asm("mov.b64 %0, {%1, %2};" : "=l"(r) : "f"(a), "f"(b)); return r;
}
__device__ __forceinline__ float2 unpack2(ull v) {
    float2 r; asm("mov.b64 {%0, %1}, %2;" : "=f"(r.x), "=f"(r.y) : "l"(v)); return r;
}
__device__ __forceinline__ unsigned ld_acquire_u32(const unsigned* p) {
    unsigned v;
    asm volatile("ld.acquire.gpu.u32 %0, [%1];" : "=r"(v) : "l"(p));
    return v;
}
__device__ __forceinline__ void red_release_add(unsigned* p, unsigned v) {
    asm volatile("red.release.gpu.global.add.u32 [%0], %1;" :: "l"(p), "r"(v) : "memory");
}
__device__ __forceinline__ float sigf(float x) {
    return __fdividef(1.0f, 1.0f + __expf(-x));
}
__device__ __forceinline__ float tanh_acc(float x) {
    float ax = fabsf(x);
    float e  = __expf(-2.0f * ax);
    float r  = __fdividef(1.0f - e, 1.0f + e);
    return copysignf(r, x);
}
__device__ __forceinline__ uint32_t h2u(__half2 h) { return *reinterpret_cast<uint32_t*>(&h); }

__device__ __forceinline__ void ldsm4(uint32_t* r, uint32_t addr) {
    asm volatile("ldmatrix.sync.aligned.m8n8.x4.shared.b16 {%0,%1,%2,%3}, [%4];"
                 : "=r"(r[0]), "=r"(r[1]), "=r"(r[2]), "=r"(r[3]) : "r"(addr));
}
__device__ __forceinline__ void mma16816(float* d, const uint32_t* a, uint32_t b0, uint32_t b1) {
    asm volatile("mma.sync.aligned.m16n8k16.row.col.f32.f16.f16.f32 "
                 "{%0,%1,%2,%3}, {%4,%5,%6,%7}, {%8,%9}, {%0,%1,%2,%3};"
                 : "+f"(d[0]), "+f"(d[1]), "+f"(d[2]), "+f"(d[3])
                 : "r"(a[0]), "r"(a[1]), "r"(a[2]), "r"(a[3]), "r"(b0), "r"(b1));
}

// smem byte offsets
#define OFF_A_HI   0          // half[128][296] = 75776
#define OFF_A_LO   75776
#define OFF_B_HI   151552     // half[32][296] = 18944
#define OFF_B_LO   170496
#define OFF_GATES  189440     // float[128][36] = 18432
#define OFF_HT     207872     // float[32][34]  = 4352
#define OFF_WOUT2  212224     // ull[32 o][17]  = 4352
#define OFF_BOUT   216576     // float[4]
#define SMEM_BYTES 216608

__global__ void __launch_bounds__(NTHR, 1)
lstm_kernel(const float* __restrict__ x, const float* __restrict__ phys,
            const float* __restrict__ Wih, const float* __restrict__ Whh,
            const float* __restrict__ bih, const float* __restrict__ bhh,
            const float* __restrict__ Wout, const float* __restrict__ bout,
            float* __restrict__ out) {
    extern __shared__ __align__(128) char smem[];
    uint32_t sbase;
    asm("{ .reg .u64 t; cvta.to.shared.u64 t, %1; cvt.u32.u64 %0, t; }" : "=r"(sbase) : "l"(smem));

    float* gates   = (float*)(smem + OFF_GATES);
    float* htile   = (float*)(smem + OFF_HT);
    ull*   wout2_s = (ull*)(smem + OFF_WOUT2);
    float* bout_s  = (float*)(smem + OFF_BOUT);

    const int tid  = threadIdx.x;
    const int cta  = blockIdx.x;
    const int grp  = cta >> 3;
    const int g8   = cta & 7;
    const int b0   = grp * BT;
    const int j0   = g8 * 32;
    const int w    = tid >> 5;
    const int lane = tid & 31;
    const int b    = tid >> 3;     // batch row 0..31 (staging/epilogue map)
    const int s    = tid & 7;      // k-slice 0..7

    // ---- zero B tiles once (pad cols 288..295 stay 0 forever) ----
    for (int i = tid; i < (2 * 18944) / 16; i += NTHR)
        ((uint4*)(smem + OFF_B_HI))[i] = make_uint4(0, 0, 0, 0);

    // ---- A = weights fp16 hi/lo, row r = 4j+gate, 592B stride ----
    for (int i = tid; i < MROWS * KP; i += NTHR) {
        int r = i / KP, k = i - r * KP;
        int j = r >> 2, g = r & 3;
        int grow = g * HH + j0 + j;
        float v = 0.0f;
        if (k < HH)        v = Whh[grow * HH + k];
        else if (k < KDIM) v = Wih[grow * II + (k - HH)];
        __half h = __float2half_rn(v);
        __half l = __float2half_rn(v - __half2float(h));
        *(__half*)(smem + OFF_A_HI + r * RB + k * 2) = h;
        *(__half*)(smem + OFF_A_LO + r * RB + k * 2) = l;
    }
    // Wout pairs over OWN j-slice, all 32 o
    for (int i = tid; i < 32 * 16; i += NTHR) {
        int o = i >> 4, jp = i & 15;
        wout2_s[o * 17 + jp] = pack2(Wout[o * HH + j0 + 2 * jp],
                                     Wout[o * HH + j0 + 2 * jp + 1]);
    }
    if (tid < 4) bout_s[tid] = bout[g8 * 4 + tid];

    // MMA fragment lane mapping (validated in R8/R9)
    const int m  = lane >> 3;
    const int r8 = lane & 7;
    const int gq = lane >> 2;
    const int tg = lane & 3;
    const uint32_t aHi = sbase + OFF_A_HI + (16 * w + ((m & 1) << 3) + r8) * RB + ((m >> 1) << 4);
    const uint32_t aLo = aHi + (OFF_A_LO - OFF_A_HI);
    const uint32_t bHi = sbase + OFF_B_HI + (((m >> 1) << 3) + r8) * RB + ((m & 1) << 4);
    const uint32_t bLo = bHi + (OFF_B_LO - OFF_B_HI);

    // bias folded into D-register init (rows 16w+gq, 16w+gq+8)
    float bias_lo, bias_hi;
    {
        int r1 = 16 * w + gq, r2 = r1 + 8;
        int j1 = r1 >> 2, gg1 = r1 & 3, j2 = r2 >> 2, gg2 = r2 & 3;
        bias_lo = bih[gg1 * HH + j0 + j1] + bhh[gg1 * HH + j0 + j1];
        bias_hi = bih[gg2 * HH + j0 + j2] + bhh[gg2 * HH + j0 + j2];
    }

    float c[4] = {0.f, 0.f, 0.f, 0.f};    // cell state: (j=tid>>3, batches 4s..4s+4)
    __syncthreads();

    for (int t = 0; t <= TT; ++t) {
        // ---- peer-independent prefetch + convert BEFORE the spin ----
        uint32_t xh0u = 0, xh1u = 0, xl0u = 0, xl1u = 0;
        if (t < TT) {
            float4 xv = *(const float4*)(x + ((size_t)t * BB + b0 + b) * II + s * 4);
            __half2 xh0 = __floats2half2_rn(xv.x, xv.y);
            __half2 xh1 = __floats2half2_rn(xv.z, xv.w);
            float2 xf0 = __half22float2(xh0), xf1 = __half22float2(xh1);
            __half2 xl0 = __floats2half2_rn(xv.x - xf0.x, xv.y - xf0.y);
            __half2 xl1 = __floats2half2_rn(xv.z - xf1.x, xv.w - xf1.y);
            xh0u = h2u(xh0); xh1u = h2u(xh1); xl0u = h2u(xl0); xl1u = h2u(xl1);
        }
        float phv = 0.0f;
        if (t > 0 && tid < 128)
            phv = phys[((size_t)(t - 1) * BB + b0 + (tid >> 2)) * OO + g8 * 4 + (tid & 3)];

        // ---- group barrier: per-warp acquire spin (64 arrivals per step) ----
        if (t > 0) {
            if (lane == 0) {
                unsigned target = 64u * (unsigned)t;
                while (ld_acquire_u32(&g_bar[grp]) < target) { }
            }
            __syncwarp();
        }

        if (t < TT) {
            // ---- stage h(t): pure fp16 copy (producer already converted) ----
            const uint4* hi4 = (const uint4*)&g_hf16_hi[t & 1][grp][b][s * 32];
            const uint4* lo4 = (const uint4*)&g_hf16_lo[t & 1][grp][b][s * 32];
            char* dhi = smem + OFF_B_HI + b * RB + s * 64;
            char* dlo = smem + OFF_B_LO + b * RB + s * 64;
#pragma unroll
            for (int mm = 0; mm < 4; ++mm) {
                *(uint4*)(dhi + mm * 16) = hi4[mm];
                *(uint4*)(dlo + mm * 16) = lo4[mm];
            }
            // stage x(t) (pre-converted) into B cols 256..287
            uint32_t off = b * RB + 512 + s * 8;
            *(uint2*)(smem + OFF_B_HI + off) = make_uint2(xh0u, xh1u);
            *(uint2*)(smem + OFF_B_LO + off) = make_uint2(xl0u, xl1u);
        }

        if (t == TT) {
            // final output for step TT-1 (no smem dependency)
            if (tid < 128) {
                int bq = tid >> 2, o = tid & 3, oc = g8 * 4 + o;
                float rnn = bout_s[o];
                const float* pp = &g_part[t & 1][grp][0][bq][oc];
#pragma unroll
                for (int p = 0; p < 8; ++p) rnn += pp[(size_t)p * BT * OO];
                size_t oi = ((size_t)(b0 + bq) * TT + (t - 1)) * OO + oc;
                out[oi] = phv + rnn;
                out[(size_t)BB * TT * OO + oi] = rnn;
            }
            break;
        }
        __syncthreads();

        // ---- gate GEMM: 3-pass fp16-split, fragments loaded once per chunk ----
        float d[4][4];
#pragma unroll
        for (int nt = 0; nt < 4; ++nt) {
            d[nt][0] = bias_lo; d[nt][1] = bias_lo;
            d[nt][2] = bias_hi; d[nt][3] = bias_hi;
        }
#pragma unroll 3
        for (int kc = 0; kc < NCHUNK; ++kc) {
            uint32_t a[4], a2[4], qh[8], ql[8];
            ldsm4(a,      aHi + kc * 32);
            ldsm4(qh,     bHi + kc * 32);
            ldsm4(qh + 4, bHi + 16 * RB + kc * 32);
            ldsm4(ql,     bLo + kc * 32);
            ldsm4(ql + 4, bLo + 16 * RB + kc * 32);
            ldsm4(a2,     aLo + kc * 32);
            mma16816(d[0], a,  qh[0], qh[1]);
            mma16816(d[1], a,  qh[2], qh[3]);
            mma16816(d[2], a,  qh[4], qh[5]);
            mma16816(d[3], a,  qh[6], qh[7]);
            mma16816(d[0], a,  ql[0], ql[1]);
            mma16816(d[1], a,  ql[2], ql[3]);
            mma16816(d[2], a,  ql[4], ql[5]);
            mma16816(d[3], a,  ql[6], ql[7]);
            mma16816(d[0], a2, qh[0], qh[1]);
            mma16816(d[1], a2, qh[2], qh[3]);
            mma16816(d[2], a2, qh[4], qh[5]);
            mma16816(d[3], a2, qh[6], qh[7]);
        }
        // D -> gates[row][batch] (stride 36)
        {
            float* glo = gates + (16 * w + gq) * 36 + 2 * tg;
            float* ghi = glo + 8 * 36;
#pragma unroll
            for (int nt = 0; nt < 4; ++nt) {
                glo[8 * nt] = d[nt][0]; glo[8 * nt + 1] = d[nt][1];
                ghi[8 * nt] = d[nt][2]; ghi[8 * nt + 1] = d[nt][3];
            }
        }

        // ---- output for step t-1 (overlaps the gates sync) ----
        if (t > 0 && tid < 128) {
            int bq = tid >> 2, o = tid & 3, oc = g8 * 4 + o;
            float rnn = bout_s[o];
            const float* pp = &g_part[t & 1][grp][0][bq][oc];
#pragma unroll
            for (int p = 0; p < 8; ++p) rnn += pp[(size_t)p * BT * OO];
            size_t oi = ((size_t)(b0 + bq) * TT + (t - 1)) * OO + oc;
            out[oi] = phv + rnn;
            out[(size_t)BB * TT * OO + oi] = rnn;
        }
        __syncthreads();

        // ---- LSTM epilogue: thread = (j = tid>>3, batches 4s..4s+4) ----
        {
            int j = tid >> 3;
            const float* gr = gates + (4 * j) * 36 + 4 * s;
            float4 vi = *(const float4*)(gr);
            float4 vf = *(const float4*)(gr + 36);
            float4 vg = *(const float4*)(gr + 72);
            float4 vo = *(const float4*)(gr + 108);
            float gi_[4] = {vi.x, vi.y, vi.z, vi.w};
            float gf_[4] = {vf.x, vf.y, vf.z, vf.w};
            float gg_[4] = {vg.x, vg.y, vg.z, vg.w};
            float go_[4] = {vo.x, vo.y, vo.z, vo.w};
#pragma unroll
            for (int i = 0; i < 4; ++i) {
                float ig = sigf(gi_[i]), fg = sigf(gf_[i]);
                float gt = tanh_acc(gg_[i]), og = sigf(go_[i]);
                float cn = fg * c[i] + ig * gt;
                c[i] = cn;
                htile[(4 * s + i) * 34 + j] = og * tanh_acc(cn);
            }
        }
        __syncthreads();

        // ---- writeback h as fp16 hi/lo (producer-side cvt) + out-proj partial ----
        {
            float f0 = htile[b * 34 + 4 * s + 0];
            float f1 = htile[b * 34 + 4 * s + 1];
            float f2 = htile[b * 34 + 4 * s + 2];
            float f3 = htile[b * 34 + 4 * s + 3];
            __half2 h01 = __floats2half2_rn(f0, f1);
            __half2 h23 = __floats2half2_rn(f2, f3);
            float2 q01 = __half22float2(h01), q23 = __half22float2(h23);
            __half2 l01 = __floats2half2_rn(f0 - q01.x, f1 - q01.y);
            __half2 l23 = __floats2half2_rn(f2 - q23.x, f3 - q23.y);
            *(uint2*)(&g_hf16_hi[(t + 1) & 1][grp][b][j0 + 4 * s]) = make_uint2(h2u(h01), h2u(h23));
            *(uint2*)(&g_hf16_lo[(t + 1) & 1][grp][b][j0 + 4 * s]) = make_uint2(h2u(l01), h2u(l23));
        }
        {
            int o4 = s * 4;
            const ull* hrow2 = (const ull*)(htile + b * 34);
            ull pa0 = 0ull, pa1 = 0ull, pa2 = 0ull, pa3 = 0ull;
#pragma unroll
            for (int jp = 0; jp < 16; ++jp) {
                ull h2 = hrow2[jp];
                ffma2(pa0, h2, wout2_s[(o4 + 0) * 17 + jp]);
                ffma2(pa1, h2, wout2_s[(o4 + 1) * 17 + jp]);
                ffma2(pa2, h2, wout2_s[(o4 + 2) * 17 + jp]);
                ffma2(pa3, h2, wout2_s[(o4 + 3) * 17 + jp]);
            }
            float2 q0 = unpack2(pa0), q1 = unpack2(pa1);
            float2 q2 = unpack2(pa2), q3 = unpack2(pa3);
            *(float4*)(&g_part[(t + 1) & 1][grp][g8][b][o4]) =
                make_float4(q0.x + q0.y, q1.x + q1.y, q2.x + q2.y, q3.x + q3.y);
        }
        // per-warp release: own STGs are ordered by red.release after syncwarp
        __syncwarp();
        if (lane == 0) red_release_add(&g_bar[grp], 1u);
    }
}

extern "C" void kernel_launch(void* const* d_in, const int* in_sizes, int n_in,
                              void* d_out, int out_size) {
    const float* x    = (const float*)d_in[0];
    const float* phys = (const float*)d_in[1];
    const float* Wih  = (const float*)d_in[2];
    const float* Whh  = (const float*)d_in[3];
    const float* bih  = (const float*)d_in[4];
    const float* bhh  = (const float*)d_in[5];
    const float* Wout = (const float*)d_in[6];
    const float* bout = (const float*)d_in[7];
    float* out = (float*)d_out;

    cudaFuncSetAttribute(lstm_kernel,
                         cudaFuncAttributeMaxDynamicSharedMemorySize,
                         SMEM_BYTES);

    init_kernel<<<(NGRP * BT * HH + 255) / 256, 256>>>();
    lstm_kernel<<<NGRP * 8, NTHR, SMEM_BYTES>>>(x, phys, Wih, Whh, bih, bhh,
                                                Wout, bout, out);
}